// round 1
// baseline (speedup 1.0000x reference)
#include <cuda_runtime.h>
#include <math.h>

// Problem shape (fixed by the dataset)
#define B_   16
#define T_   2048
#define D_   1024
#define V_   640
#define M_   (B_ * T_)     // 32768 rows

// GEMM tiling
#define BM 128
#define BN 128
#define BK 16
#define TM 8
#define TN 8
#define NTHREADS 256

// Scratch (no device allocation allowed -> __device__ globals)
__device__ int   g_idx[M_];
__device__ float g_ent[T_];

// ---------------------------------------------------------------------------
// Kernel 1: fused logits GEMM + gumbel add + per-row argmax
//   logits[m, v] = z[m, :] . codebook[v, :]  (+ gumbel[m, v])
//   g_idx[m] = argmax_v  (tie -> lowest v, matching jnp.argmax)
// ---------------------------------------------------------------------------
__global__ __launch_bounds__(NTHREADS) void gemm_argmax_kernel(
    const float* __restrict__ z,
    const float* __restrict__ cb,
    const float* __restrict__ gum)
{
    __shared__ float As[BK][BM + 4];   // As[k][m]
    __shared__ float Bs[BK][BN + 4];   // Bs[k][n]
    __shared__ float redv[BM][17];
    __shared__ int   redc[BM][17];

    const int tid = threadIdx.x;
    const int tx  = tid & 15;          // 16 threads across N
    const int ty  = tid >> 4;          // 16 threads across M
    const int m0  = blockIdx.x * BM;

    float bestv[TM];
    int   bestc[TM];
#pragma unroll
    for (int i = 0; i < TM; i++) { bestv[i] = -1e30f; bestc[i] = 0; }

    for (int n0 = 0; n0 < V_; n0 += BN) {
        // Accumulators initialized with gumbel so argmax target is acc directly.
        float acc[TM][TN];
#pragma unroll
        for (int i = 0; i < TM; i++) {
            const float4* gp = (const float4*)&gum[(size_t)(m0 + ty * TM + i) * V_ + n0 + tx * TN];
            float4 g0 = gp[0];
            float4 g1 = gp[1];
            acc[i][0] = g0.x; acc[i][1] = g0.y; acc[i][2] = g0.z; acc[i][3] = g0.w;
            acc[i][4] = g1.x; acc[i][5] = g1.y; acc[i][6] = g1.z; acc[i][7] = g1.w;
        }

        for (int kt = 0; kt < D_; kt += BK) {
            // Load A (z) and B (codebook) tiles, transposed into [k][row] layout.
            // 128 rows x 16 k = 512 float4 per matrix; 2 float4 per thread.
#pragma unroll
            for (int r = 0; r < 2; r++) {
                int p   = tid + r * NTHREADS;   // 0..511
                int row = p >> 2;
                int k4  = (p & 3) * 4;
                float4 va = *(const float4*)&z [(size_t)(m0 + row) * D_ + kt + k4];
                As[k4 + 0][row] = va.x; As[k4 + 1][row] = va.y;
                As[k4 + 2][row] = va.z; As[k4 + 3][row] = va.w;
                float4 vb = *(const float4*)&cb[(size_t)(n0 + row) * D_ + kt + k4];
                Bs[k4 + 0][row] = vb.x; Bs[k4 + 1][row] = vb.y;
                Bs[k4 + 2][row] = vb.z; Bs[k4 + 3][row] = vb.w;
            }
            __syncthreads();

#pragma unroll
            for (int k = 0; k < BK; k++) {
                float a[TM], b[TN];
                *(float4*)&a[0] = *(const float4*)&As[k][ty * TM];
                *(float4*)&a[4] = *(const float4*)&As[k][ty * TM + 4];
                *(float4*)&b[0] = *(const float4*)&Bs[k][tx * TN];
                *(float4*)&b[4] = *(const float4*)&Bs[k][tx * TN + 4];
#pragma unroll
                for (int i = 0; i < TM; i++)
#pragma unroll
                    for (int j = 0; j < TN; j++)
                        acc[i][j] = fmaf(a[i], b[j], acc[i][j]);
            }
            __syncthreads();
        }

        // Per-thread argmax update (ascending j, strict > -> first occurrence wins)
#pragma unroll
        for (int i = 0; i < TM; i++) {
#pragma unroll
            for (int j = 0; j < TN; j++) {
                if (acc[i][j] > bestv[i]) {
                    bestv[i] = acc[i][j];
                    bestc[i] = n0 + tx * TN + j;
                }
            }
        }
    }

    // Cross-thread reduce: 16 threads per row.
    __syncthreads();
#pragma unroll
    for (int i = 0; i < TM; i++) {
        redv[ty * TM + i][tx] = bestv[i];
        redc[ty * TM + i][tx] = bestc[i];
    }
    __syncthreads();
    if (tid < BM) {
        float bv = redv[tid][0];
        int   bc = redc[tid][0];
#pragma unroll
        for (int t = 1; t < 16; t++) {
            // ascending tx => ascending column, strict > keeps lowest index
            if (redv[tid][t] > bv) { bv = redv[tid][t]; bc = redc[tid][t]; }
        }
        g_idx[m0 + tid] = bc;
    }
}

// ---------------------------------------------------------------------------
// Kernel 2: gather rows of W_p  -> quantized output
// ---------------------------------------------------------------------------
__global__ __launch_bounds__(256) void gather_kernel(
    const float* __restrict__ Wp, float* __restrict__ out)
{
    const int m = blockIdx.x;
    const int v = g_idx[m];
    const float4* src = (const float4*)&Wp[(size_t)v * D_];
    float4* dst = (float4*)&out[(size_t)m * D_];
    dst[threadIdx.x] = src[threadIdx.x];   // 256 * float4 = 1024 floats
}

// ---------------------------------------------------------------------------
// Kernel 3: per-t entropy from index counts over the batch dim
// ---------------------------------------------------------------------------
__global__ __launch_bounds__(256) void entropy_kernel()
{
    const int t = blockIdx.x * 256 + threadIdx.x;
    if (t >= T_) return;
    int ids[B_];
#pragma unroll
    for (int b = 0; b < B_; b++) ids[b] = g_idx[b * T_ + t];
    float H = 0.0f;
#pragma unroll
    for (int b = 0; b < B_; b++) {
        bool first = true;
#pragma unroll
        for (int b2 = 0; b2 < B_; b2++) {
            if (b2 < b && ids[b2] == ids[b]) first = false;
        }
        if (first) {
            int c = 0;
#pragma unroll
            for (int b2 = 0; b2 < B_; b2++) c += (ids[b2] == ids[b]);
            float p = (float)c * (1.0f / (float)B_);
            H -= p * logf(p + 1e-10f);
        }
    }
    g_ent[t] = H;
}

// ---------------------------------------------------------------------------
// Kernel 4: deterministic tree-reduce of per-t entropies -> scalar loss
// ---------------------------------------------------------------------------
__global__ __launch_bounds__(256) void loss_reduce_kernel(float* __restrict__ out, int off)
{
    __shared__ float s[256];
    float sum = 0.0f;
    for (int i = threadIdx.x; i < T_; i += 256) sum += g_ent[i];
    s[threadIdx.x] = sum;
    __syncthreads();
    for (int stride = 128; stride > 0; stride >>= 1) {
        if (threadIdx.x < stride) s[threadIdx.x] += s[threadIdx.x + stride];
        __syncthreads();
    }
    if (threadIdx.x == 0 && off >= 0) out[off] = s[0] / (float)T_;
}

// ---------------------------------------------------------------------------
extern "C" void kernel_launch(void* const* d_in, const int* in_sizes, int n_in,
                              void* d_out, int out_size)
{
    const float* z   = (const float*)d_in[0];  // [B,T,D]
    const float* cb  = (const float*)d_in[1];  // [V,D]
    const float* Wp  = (const float*)d_in[2];  // [V,D]
    const float* gum = (const float*)d_in[3];  // [B,T,V]
    float* out = (float*)d_out;

    gemm_argmax_kernel<<<M_ / BM, NTHREADS>>>(z, cb, gum);
    gather_kernel<<<M_, 256>>>(Wp, out);
    entropy_kernel<<<(T_ + 255) / 256, 256>>>();
    int off = (out_size > M_ * D_) ? (out_size - 1) : -1;
    loss_reduce_kernel<<<1, 256>>>(out, off);
}

// round 2
// speedup vs baseline: 1.1075x; 1.1075x over previous
#include <cuda_runtime.h>
#include <math.h>

// Problem shape (fixed by the dataset)
#define B_   16
#define T_   2048
#define D_   1024
#define V_   640
#define M_   (B_ * T_)     // 32768 rows

// GEMM tiling
#define BM 128
#define BN 128
#define BK 16
#define TM 8
#define TN 8
#define NTHREADS 256

typedef unsigned long long u64;

// Packed dual-f32 ops (Blackwell sm_103a; PTX-only, ptxas never auto-fuses)
#define FMA_F32X2(d, a, b) \
    asm("fma.rn.f32x2 %0, %1, %2, %0;" : "+l"(d) : "l"(a), "l"(b))
#define PACK_DUP_F32X2(out, r) \
    asm("mov.b64 %0, {%1, %1};" : "=l"(out) : "r"(r))
#define UNPACK_F32X2(lo, hi, in) \
    asm("mov.b64 {%0, %1}, %2;" : "=r"(lo), "=r"(hi) : "l"(in))

// Scratch (no device allocation allowed -> __device__ globals)
__device__ int   g_idx[M_];
__device__ float g_ent[T_];

// ---------------------------------------------------------------------------
// Kernel 1: fused logits GEMM + gumbel add + per-row argmax
//   score[m, v] = z[m, :] . codebook[v, :] + gumbel[m, v]
//   g_idx[m] = argmax_v  (tie -> lowest v, matching jnp.argmax)
// Inner product uses packed fma.rn.f32x2 (2 f32 FMAs per fma-pipe issue).
// ---------------------------------------------------------------------------
__global__ __launch_bounds__(NTHREADS) void gemm_argmax_kernel(
    const float* __restrict__ z,
    const float* __restrict__ cb,
    const float* __restrict__ gum)
{
    __shared__ float As[BK][BM + 4];   // As[k][m]
    __shared__ float Bs[BK][BN + 4];   // Bs[k][n]
    __shared__ float redv[BM][17];
    __shared__ int   redc[BM][17];

    const int tid = threadIdx.x;
    const int tx  = tid & 15;          // 16 threads across N
    const int ty  = tid >> 4;          // 16 threads across M
    const int m0  = blockIdx.x * BM;

    float bestv[TM];
    int   bestc[TM];
#pragma unroll
    for (int i = 0; i < TM; i++) { bestv[i] = -1e30f; bestc[i] = 0; }

    for (int n0 = 0; n0 < V_; n0 += BN) {
        // Accumulators (packed f32x2 pairs along N), initialized with gumbel
        // so the argmax target is the accumulator directly.
        u64 acc2[TM][TN / 2];
#pragma unroll
        for (int i = 0; i < TM; i++) {
            // gumbel row is 32-byte aligned at this offset (tx*TN*4 bytes)
            const u64* gp = (const u64*)&gum[(size_t)(m0 + ty * TM + i) * V_ + n0 + tx * TN];
            acc2[i][0] = gp[0]; acc2[i][1] = gp[1];
            acc2[i][2] = gp[2]; acc2[i][3] = gp[3];
        }

        for (int kt = 0; kt < D_; kt += BK) {
            // Load A (z) and B (codebook) tiles, transposed into [k][row] layout.
            // 128 rows x 16 k = 512 float4 per matrix; 2 float4 per thread.
#pragma unroll
            for (int r = 0; r < 2; r++) {
                int p   = tid + r * NTHREADS;   // 0..511
                int row = p >> 2;
                int k4  = (p & 3) * 4;
                float4 va = *(const float4*)&z [(size_t)(m0 + row) * D_ + kt + k4];
                As[k4 + 0][row] = va.x; As[k4 + 1][row] = va.y;
                As[k4 + 2][row] = va.z; As[k4 + 3][row] = va.w;
                float4 vb = *(const float4*)&cb[(size_t)(n0 + row) * D_ + kt + k4];
                Bs[k4 + 0][row] = vb.x; Bs[k4 + 1][row] = vb.y;
                Bs[k4 + 2][row] = vb.z; Bs[k4 + 3][row] = vb.w;
            }
            __syncthreads();

#pragma unroll
            for (int k = 0; k < BK; k++) {
                float a[TM];
                u64   a2[TM], b2[TN / 2];
                // a: 2x LDS.128 (16-way broadcast within warp)
                *(float4*)&a[0] = *(const float4*)&As[k][ty * TM];
                *(float4*)&a[4] = *(const float4*)&As[k][ty * TM + 4];
                // b: 2x LDS.128 viewed as 4 packed f32x2 pairs (32B-aligned)
                {
                    const u64* bp = (const u64*)&Bs[k][tx * TN];
                    b2[0] = bp[0]; b2[1] = bp[1]; b2[2] = bp[2]; b2[3] = bp[3];
                }
                // duplicate a into both packed halves (alu pipe, parallel to fma)
#pragma unroll
                for (int i = 0; i < TM; i++) PACK_DUP_F32X2(a2[i], __float_as_uint(a[i]));
#pragma unroll
                for (int i = 0; i < TM; i++)
#pragma unroll
                    for (int jp = 0; jp < TN / 2; jp++)
                        FMA_F32X2(acc2[i][jp], a2[i], b2[jp]);
            }
            __syncthreads();
        }

        // Per-thread argmax update (ascending j, strict > -> first occurrence wins)
#pragma unroll
        for (int i = 0; i < TM; i++) {
#pragma unroll
            for (int jp = 0; jp < TN / 2; jp++) {
                unsigned lo, hi;
                UNPACK_F32X2(lo, hi, acc2[i][jp]);
                float vlo = __uint_as_float(lo);
                float vhi = __uint_as_float(hi);
                int   j   = 2 * jp;
                if (vlo > bestv[i]) { bestv[i] = vlo; bestc[i] = n0 + tx * TN + j; }
                if (vhi > bestv[i]) { bestv[i] = vhi; bestc[i] = n0 + tx * TN + j + 1; }
            }
        }
    }

    // Cross-thread reduce: 16 threads per row.
    __syncthreads();
#pragma unroll
    for (int i = 0; i < TM; i++) {
        redv[ty * TM + i][tx] = bestv[i];
        redc[ty * TM + i][tx] = bestc[i];
    }
    __syncthreads();
    if (tid < BM) {
        float bv = redv[tid][0];
        int   bc = redc[tid][0];
#pragma unroll
        for (int t = 1; t < 16; t++) {
            // ascending tx => ascending column, strict > keeps lowest index
            if (redv[tid][t] > bv) { bv = redv[tid][t]; bc = redc[tid][t]; }
        }
        g_idx[m0 + tid] = bc;
    }
}

// ---------------------------------------------------------------------------
// Kernel 2: gather rows of W_p  -> quantized output
// ---------------------------------------------------------------------------
__global__ __launch_bounds__(256) void gather_kernel(
    const float* __restrict__ Wp, float* __restrict__ out)
{
    const int m = blockIdx.x;
    const int v = g_idx[m];
    const float4* src = (const float4*)&Wp[(size_t)v * D_];
    float4* dst = (float4*)&out[(size_t)m * D_];
    dst[threadIdx.x] = src[threadIdx.x];   // 256 * float4 = 1024 floats
}

// ---------------------------------------------------------------------------
// Kernel 3: per-t entropy from index counts over the batch dim
// ---------------------------------------------------------------------------
__global__ __launch_bounds__(256) void entropy_kernel()
{
    const int t = blockIdx.x * 256 + threadIdx.x;
    if (t >= T_) return;
    int ids[B_];
#pragma unroll
    for (int b = 0; b < B_; b++) ids[b] = g_idx[b * T_ + t];
    float H = 0.0f;
#pragma unroll
    for (int b = 0; b < B_; b++) {
        bool first = true;
#pragma unroll
        for (int b2 = 0; b2 < B_; b2++) {
            if (b2 < b && ids[b2] == ids[b]) first = false;
        }
        if (first) {
            int c = 0;
#pragma unroll
            for (int b2 = 0; b2 < B_; b2++) c += (ids[b2] == ids[b]);
            float p = (float)c * (1.0f / (float)B_);
            H -= p * logf(p + 1e-10f);
        }
    }
    g_ent[t] = H;
}

// ---------------------------------------------------------------------------
// Kernel 4: deterministic tree-reduce of per-t entropies -> scalar loss
// ---------------------------------------------------------------------------
__global__ __launch_bounds__(256) void loss_reduce_kernel(float* __restrict__ out, int off)
{
    __shared__ float s[256];
    float sum = 0.0f;
    for (int i = threadIdx.x; i < T_; i += 256) sum += g_ent[i];
    s[threadIdx.x] = sum;
    __syncthreads();
    for (int stride = 128; stride > 0; stride >>= 1) {
        if (threadIdx.x < stride) s[threadIdx.x] += s[threadIdx.x + stride];
        __syncthreads();
    }
    if (threadIdx.x == 0 && off >= 0) out[off] = s[0] / (float)T_;
}

// ---------------------------------------------------------------------------
extern "C" void kernel_launch(void* const* d_in, const int* in_sizes, int n_in,
                              void* d_out, int out_size)
{
    const float* z   = (const float*)d_in[0];  // [B,T,D]
    const float* cb  = (const float*)d_in[1];  // [V,D]
    const float* Wp  = (const float*)d_in[2];  // [V,D]
    const float* gum = (const float*)d_in[3];  // [B,T,V]
    float* out = (float*)d_out;

    gemm_argmax_kernel<<<M_ / BM, NTHREADS>>>(z, cb, gum);
    gather_kernel<<<M_, 256>>>(Wp, out);
    entropy_kernel<<<(T_ + 255) / 256, 256>>>();
    int off = (out_size > M_ * D_) ? (out_size - 1) : -1;
    loss_reduce_kernel<<<1, 256>>>(out, off);
}

// round 5
// speedup vs baseline: 2.0650x; 1.8644x over previous
#include <cuda_runtime.h>
#include <cuda_bf16.h>
#include <math.h>
#include <stdint.h>

// ---------------------------------------------------------------- shapes
#define B_   16
#define T_   2048
#define D_   1024
#define V_   640
#define M_   (B_ * T_)        // 32768 rows

#define DELTA 3.0f            // candidate margin (~55 sigma of bf16 GEMM error)
#define MAXC  16

// GEMM tiling
#define BMT   128              // CTA rows
#define BNT   128              // N chunk (5 chunks cover V=640)
#define KT    64               // k elems per stage (128B rows)
#define NCHUNK (V_ / BNT)      // 5
#define NKT   (D_ / KT)        // 16 tiles per chunk
#define NT_TOT (NCHUNK * NKT)  // 80 global tiles

// dynamic SMEM layout (bytes)
#define SM_A    0              // 2 stages x 16384
#define SM_B    32768          // 2 stages x 16384
#define SM_SC   65536          // float[128*132] = 67584
#define SMEM_TOTAL 133120

// ---------------------------------------------------------------- scratch
__device__ int           g_idx[M_];
__device__ float         g_ent[T_];
__device__ __nv_bfloat16 g_z16[M_ * D_];
__device__ __nv_bfloat16 g_cb16[V_ * D_];
__device__ int           g_ncand[M_];
__device__ int           g_cand[M_][MAXC];

// ---------------------------------------------------------------- PTX helpers
__device__ __forceinline__ uint32_t smem_u32(const void* p) {
    uint32_t a;
    asm("{ .reg .u64 t; cvta.to.shared.u64 t, %1; cvt.u32.u64 %0, t; }" : "=r"(a) : "l"(p));
    return a;
}
__device__ __forceinline__ uint32_t bf2(float lo, float hi) {
    uint32_t r;  // d.hi = cvt(first src), d.lo = cvt(second src)
    asm("cvt.rn.bf16x2.f32 %0, %1, %2;" : "=r"(r) : "f"(hi), "f"(lo));
    return r;
}
#define CP16(dst, src) \
    asm volatile("cp.async.cg.shared.global [%0], [%1], 16;" :: "r"(dst), "l"(src) : "memory")
#define CP_COMMIT() asm volatile("cp.async.commit_group;" ::: "memory")
#define CP_WAIT1()  asm volatile("cp.async.wait_group 1;" ::: "memory")

#define LDMX4(r, a) \
    asm volatile("ldmatrix.sync.aligned.m8n8.x4.shared.b16 {%0,%1,%2,%3}, [%4];" \
        : "=r"((r)[0]), "=r"((r)[1]), "=r"((r)[2]), "=r"((r)[3]) : "r"(a))

#define MMA16816(d, a, b0, b1) \
    asm volatile("mma.sync.aligned.m16n8k16.row.col.f32.bf16.bf16.f32 " \
        "{%0,%1,%2,%3}, {%4,%5,%6,%7}, {%8,%9}, {%0,%1,%2,%3};" \
        : "+f"((d)[0]), "+f"((d)[1]), "+f"((d)[2]), "+f"((d)[3]) \
        : "r"((a)[0]), "r"((a)[1]), "r"((a)[2]), "r"((a)[3]), "r"(b0), "r"(b1))

// ---------------------------------------------------------------- f32 -> bf16 converts
__global__ __launch_bounds__(256) void cvt_z_kernel(const float* __restrict__ z) {
    size_t i = (size_t)blockIdx.x * 256 + threadIdx.x;   // 8 floats each
    const float4* p = (const float4*)z + i * 2;
    float4 v0 = p[0], v1 = p[1];
    ((uint4*)g_z16)[i] = make_uint4(bf2(v0.x, v0.y), bf2(v0.z, v0.w),
                                    bf2(v1.x, v1.y), bf2(v1.z, v1.w));
}
__global__ __launch_bounds__(256) void cvt_cb_kernel(const float* __restrict__ cb) {
    size_t i = (size_t)blockIdx.x * 256 + threadIdx.x;   // 8 floats each
    const float4* p = (const float4*)cb + i * 2;
    float4 v0 = p[0], v1 = p[1];
    ((uint4*)g_cb16)[i] = make_uint4(bf2(v0.x, v0.y), bf2(v0.z, v0.w),
                                    bf2(v1.x, v1.y), bf2(v1.z, v1.w));
}

// ---------------------------------------------------------------- GEMM + candidates
// grid 256 CTAs, 256 threads. CTA = rows [m0, m0+128). 5 N-chunks of 128.
// approx score = bf16(z).bf16(cb) + gumbel; keep all v within DELTA of row max.
__device__ __forceinline__ void load_tile(uint32_t smb, int m0, int gt, int stage) {
    if (gt < NT_TOT) {
        const int ch = gt >> 4, tt = gt & 15;
        const int n0 = ch * BNT, k0 = tt * KT;
        const int tid = threadIdx.x;
#pragma unroll
        for (int r = 0; r < 4; r++) {
            int p = tid + r * 256;          // 0..1023
            int row = p >> 3, c8 = p & 7;
            uint32_t sw = (uint32_t)((c8 ^ (row & 7)) << 4);
            uint32_t da = smb + SM_A + stage * 16384 + row * 128 + sw;
            CP16(da, g_z16 + (size_t)(m0 + row) * D_ + k0 + c8 * 8);
            uint32_t db = smb + SM_B + stage * 16384 + row * 128 + sw;
            CP16(db, g_cb16 + (size_t)(n0 + row) * D_ + k0 + c8 * 8);
        }
    }
    CP_COMMIT();
}

__global__ __launch_bounds__(256, 1) void gemm_cand_kernel(const float* __restrict__ gum)
{
    extern __shared__ char sm[];
    float* scb = (float*)(sm + SM_SC);
    const uint32_t smb = smem_u32(sm);
    const int tid  = threadIdx.x;
    const int lane = tid & 31;
    const int wid  = tid >> 5;
    const int wm   = (wid & 3) * 32;     // warp row base
    const int wn   = (wid >> 2) * 64;    // warp col base
    const int m0   = blockIdx.x * BMT;

    // per-row candidate state (owner threads tid < 128, one row each)
    float bestv = -1e30f;
    float cs[MAXC];
    int   cvd[MAXC];
    int   nc = 0, ovf = 0;

    load_tile(smb, m0, 0, 0);
    load_tile(smb, m0, 1, 1);

    for (int ch = 0; ch < NCHUNK; ch++) {
        const int v0 = ch * BNT;
        float acc[2][8][4];
#pragma unroll
        for (int mi = 0; mi < 2; mi++)
#pragma unroll
            for (int nj = 0; nj < 8; nj++)
#pragma unroll
                for (int q = 0; q < 4; q++) acc[mi][nj][q] = 0.0f;

        for (int t = 0; t < NKT; t++) {
            const int gt = ch * NKT + t;
            const int s  = gt & 1;
            CP_WAIT1();
            __syncthreads();

            const uint32_t sa = smb + SM_A + s * 16384;
            const uint32_t sb = smb + SM_B + s * 16384;
#pragma unroll
            for (int kk = 0; kk < 4; kk++) {
                const int csel = kk * 2 + (lane >> 4);
                const int rsel = lane & 15;
                uint32_t a[2][4], bb[4][4];
#pragma unroll
                for (int mi = 0; mi < 2; mi++) {
                    int row = wm + mi * 16 + rsel;
                    LDMX4(a[mi], sa + row * 128 + ((csel ^ (row & 7)) << 4));
                }
#pragma unroll
                for (int g = 0; g < 4; g++) {
                    int row = wn + g * 16 + rsel;
                    LDMX4(bb[g], sb + row * 128 + ((csel ^ (row & 7)) << 4));
                }
#pragma unroll
                for (int mi = 0; mi < 2; mi++)
#pragma unroll
                    for (int g = 0; g < 4; g++) {
                        MMA16816(acc[mi][2 * g],     a[mi], bb[g][0], bb[g][2]);
                        MMA16816(acc[mi][2 * g + 1], a[mi], bb[g][1], bb[g][3]);
                    }
            }
            __syncthreads();
            load_tile(smb, m0, gt + 2, s);   // next tile (or next chunk's head) into stage s
        }

        // ---- epilogue: scores = acc + gumbel -> smem, then candidate scan ----
        // (cp.async for next chunk is already in flight and overlaps this)
#pragma unroll
        for (int mi = 0; mi < 2; mi++)
#pragma unroll
            for (int nj = 0; nj < 8; nj++) {
                int lr = wm + mi * 16 + (lane >> 2);
                int lc = wn + nj * 8 + ((lane & 3) << 1);
                float2 g0 = *(const float2*)(gum + (size_t)(m0 + lr) * V_ + v0 + lc);
                float2 g1 = *(const float2*)(gum + (size_t)(m0 + lr + 8) * V_ + v0 + lc);
                float2 s0 = make_float2(acc[mi][nj][0] + g0.x, acc[mi][nj][1] + g0.y);
                float2 s1 = make_float2(acc[mi][nj][2] + g1.x, acc[mi][nj][3] + g1.y);
                *(float2*)&scb[lr * 132 + lc]       = s0;
                *(float2*)&scb[(lr + 8) * 132 + lc] = s1;
            }
        __syncthreads();
        if (tid < BMT) {
            const float* srow = scb + tid * 132;
            for (int c = 0; c < BNT; c++) {
                float sc = srow[c];
                if (sc > bestv - DELTA) {
                    if (nc < MAXC) { cs[nc] = sc; cvd[nc] = v0 + c; nc++; }
                    else ovf = 1;
                    if (sc > bestv) bestv = sc;
                }
            }
        }
        __syncthreads();   // scan done before next chunk's epilogue overwrites scb
    }

    if (tid < BMT) {
        int m = m0 + tid;
        if (ovf) g_ncand[m] = 1000;
        else {
            int o = 0;
            for (int i = 0; i < nc; i++)
                if (cs[i] > bestv - DELTA) g_cand[m][o++] = cvd[i];  // ascending v
            g_ncand[m] = o;
        }
    }
}

// ---------------------------------------------------------------- exact rescore + gather
__global__ __launch_bounds__(128) void rescore_gather_kernel(
    const float* __restrict__ z, const float* __restrict__ cb,
    const float* __restrict__ Wp, const float* __restrict__ gum,
    float* __restrict__ out)
{
    const int m = blockIdx.x;
    const int tid = threadIdx.x, lane = tid & 31, w = tid >> 5;
    __shared__ float part[4];
    __shared__ int s_best;

    int nc = g_ncand[m];
    int bvv;
    if (nc == 1) {
        bvv = g_cand[m][0];           // unique candidate == exact argmax
        if (tid == 0) g_idx[m] = bvv;
    } else {
        float4 z0 = *(const float4*)(z + (size_t)m * D_ + tid * 8);
        float4 z1 = *(const float4*)(z + (size_t)m * D_ + tid * 8 + 4);
        bool full = (nc > MAXC) || (nc <= 0);
        int n = full ? V_ : nc;
        float best = -1e30f;
        for (int i = 0; i < n; i++) {
            int v = full ? i : g_cand[m][i];
            const float4* cp = (const float4*)(cb + (size_t)v * D_ + tid * 8);
            float4 c0 = cp[0], c1 = cp[1];
            float p = 0.0f;
            p = fmaf(z0.x, c0.x, p); p = fmaf(z0.y, c0.y, p);
            p = fmaf(z0.z, c0.z, p); p = fmaf(z0.w, c0.w, p);
            p = fmaf(z1.x, c1.x, p); p = fmaf(z1.y, c1.y, p);
            p = fmaf(z1.z, c1.z, p); p = fmaf(z1.w, c1.w, p);
#pragma unroll
            for (int o = 16; o; o >>= 1) p += __shfl_down_sync(0xffffffffu, p, o);
            if (lane == 0) part[w] = p;
            __syncthreads();
            if (tid == 0) {
                float sc = part[0] + part[1] + part[2] + part[3] + gum[(size_t)m * V_ + v];
                if (sc > best) { best = sc; s_best = v; }  // ascending v, strict >
            }
            __syncthreads();
        }
        if (tid == 0) g_idx[m] = s_best;
        bvv = s_best;
    }
    const float4* src = (const float4*)(Wp + (size_t)bvv * D_ + tid * 8);
    float4* dst = (float4*)(out + (size_t)m * D_ + tid * 8);
    dst[0] = src[0]; dst[1] = src[1];
}

// ---------------------------------------------------------------- entropy + loss
__global__ __launch_bounds__(256) void entropy_kernel()
{
    const int t = blockIdx.x * 256 + threadIdx.x;
    if (t >= T_) return;
    int ids[B_];
#pragma unroll
    for (int b = 0; b < B_; b++) ids[b] = g_idx[b * T_ + t];
    float H = 0.0f;
#pragma unroll
    for (int b = 0; b < B_; b++) {
        bool first = true;
#pragma unroll
        for (int b2 = 0; b2 < B_; b2++)
            if (b2 < b && ids[b2] == ids[b]) first = false;
        if (first) {
            int c = 0;
#pragma unroll
            for (int b2 = 0; b2 < B_; b2++) c += (ids[b2] == ids[b]);
            float p = (float)c * (1.0f / (float)B_);
            H -= p * logf(p + 1e-10f);
        }
    }
    g_ent[t] = H;
}

__global__ __launch_bounds__(256) void loss_reduce_kernel(float* __restrict__ out, int off)
{
    __shared__ float s[256];
    float sum = 0.0f;
    for (int i = threadIdx.x; i < T_; i += 256) sum += g_ent[i];
    s[threadIdx.x] = sum;
    __syncthreads();
    for (int stride = 128; stride > 0; stride >>= 1) {
        if (threadIdx.x < stride) s[threadIdx.x] += s[threadIdx.x + stride];
        __syncthreads();
    }
    if (threadIdx.x == 0 && off >= 0) out[off] = s[0] / (float)T_;
}

// ----------------------------------------------------------------
extern "C" void kernel_launch(void* const* d_in, const int* in_sizes, int n_in,
                              void* d_out, int out_size)
{
    const float* z   = (const float*)d_in[0];  // [B,T,D]
    const float* cb  = (const float*)d_in[1];  // [V,D]
    const float* Wp  = (const float*)d_in[2];  // [V,D]
    const float* gum = (const float*)d_in[3];  // [B,T,V]
    float* out = (float*)d_out;

    cudaFuncSetAttribute(gemm_cand_kernel,
                         cudaFuncAttributeMaxDynamicSharedMemorySize, SMEM_TOTAL);

    cvt_z_kernel <<<M_ * D_ / 8 / 256, 256>>>(z);
    cvt_cb_kernel<<<V_ * D_ / 8 / 256, 256>>>(cb);
    gemm_cand_kernel<<<M_ / BMT, 256, SMEM_TOTAL>>>(gum);
    rescore_gather_kernel<<<M_, 128>>>(z, cb, Wp, gum, out);
    entropy_kernel<<<(T_ + 255) / 256, 256>>>();
    int off = (out_size > M_ * D_) ? (out_size - 1) : -1;
    loss_reduce_kernel<<<1, 256>>>(out, off);
}